// round 7
// baseline (speedup 1.0000x reference)
#include <cuda_runtime.h>
#include <cuda_bf16.h>
#include <cstdint>

#define BATCH 8
#define NSEQ 2048
#define CDIM 320
#define HEADS 5
#define HDIM 64
#define MTOT (BATCH*NSEQ)      // 16384
#define QSCALE (0.125f * 1.4426950408889634f)   // scale * log2(e), folded into Q

#define XFLOATS (MTOT*CDIM)        // 5242880
#define WQFLOATS (3*CDIM*CDIM)     // 307200
#define WPFLOATS (CDIM*CDIM)       // 102400

// Scratch (static device globals; values pre-rounded to tf32 by producers)
__device__ float g_q  [BATCH*HEADS*NSEQ*HDIM];   // [B,H,N,D]
__device__ float g_k  [BATCH*HEADS*NSEQ*HDIM];   // [B,H,N,D]
__device__ float g_vt [BATCH*HEADS*HDIM*NSEQ];   // [B,H,D,N]  (V transposed)
__device__ float g_att[MTOT*CDIM];               // doubles as tf32(X) before flash
__device__ float g_wqr[WQFLOATS];                // tf32(w_qkv)
__device__ float g_wpr[WPFLOATS];                // tf32(w_proj)

__device__ __forceinline__ uint32_t f2t(float x) {
    uint32_t u;
    asm("cvt.rna.tf32.f32 %0, %1;" : "=r"(u) : "f"(x));
    return u;
}
__device__ __forceinline__ float ex2(float x) {
    float y;
    asm("ex2.approx.f32 %0, %1;" : "=f"(y) : "f"(x));
    return y;
}
__device__ __forceinline__ uint32_t fb(float x) { return __float_as_uint(x); }

// D = A(16x8,row) * B(8x8,col) + D, tf32 in, fp32 accum
__device__ __forceinline__ void mma8(float* c,
                                     uint32_t a0, uint32_t a1, uint32_t a2, uint32_t a3,
                                     uint32_t b0, uint32_t b1) {
    asm volatile(
        "mma.sync.aligned.m16n8k8.row.col.f32.tf32.tf32.f32 "
        "{%0,%1,%2,%3}, {%4,%5,%6,%7}, {%8,%9}, {%0,%1,%2,%3};"
        : "+f"(c[0]), "+f"(c[1]), "+f"(c[2]), "+f"(c[3])
        : "r"(a0), "r"(a1), "r"(a2), "r"(a3), "r"(b0), "r"(b1));
}

#define CP16(dst_u32, src) \
    asm volatile("cp.async.cg.shared.global [%0], [%1], 16;" :: "r"(dst_u32), "l"(src))
#define CP_COMMIT() asm volatile("cp.async.commit_group;")
#define CP_WAIT0()  asm volatile("cp.async.wait_group 0;")

// ---------------------------------------------------------------------------
// Kernel 0: prepass — tf32-round X -> g_att, w_qkv -> g_wqr, w_proj -> g_wpr.
// Removes all redundant per-tile cvt work from the GEMM fills.
// ---------------------------------------------------------------------------
#define PRE_TOTAL ((XFLOATS + WQFLOATS + WPFLOATS) / 4)   // 1413120 float4s
__global__ __launch_bounds__(256) void pre_round(const float* __restrict__ X,
                                                 const float* __restrict__ Wq,
                                                 const float* __restrict__ Wp) {
    int i = blockIdx.x * 256 + threadIdx.x;
    if (i >= PRE_TOTAL) return;
    const float4* src;
    float4* dst;
    int j;
    if (i < XFLOATS / 4)                { src = (const float4*)X;  dst = (float4*)g_att; j = i; }
    else if (i < (XFLOATS+WQFLOATS)/4)  { src = (const float4*)Wq; dst = (float4*)g_wqr; j = i - XFLOATS/4; }
    else                                { src = (const float4*)Wp; dst = (float4*)g_wpr; j = i - (XFLOATS+WQFLOATS)/4; }
    float4 v = src[j];
    uint32_t t[4] = {f2t(v.x), f2t(v.y), f2t(v.z), f2t(v.w)};
    dst[j] = *(float4*)t;
}

// ---------------------------------------------------------------------------
// Kernel 1: QKV GEMM on pre-rounded data. BM=128, BN=64, BK=32, 8 warps.
// cp.async double-buffered fills (raw 16B copies). LDS.64 fragments
// (k-reorder trick). Epilogue: Q pre-scaled by scale*log2e, V transposed.
// ---------------------------------------------------------------------------
#define QA_ST (128 * 40)
#define QB_ST (64 * 40)
__global__ __launch_bounds__(256) void qkv_gemm() {
    extern __shared__ uint32_t smq[];   // As[2][128][40] | Bs[2][64][40]
    uint32_t smb;
    { uint64_t a = __cvta_generic_to_shared(smq); smb = (uint32_t)a; }

    const int tid = threadIdx.x;
    const int wid = tid >> 5, lane = tid & 31;
    const int g = lane >> 2, t = lane & 3;
    const int m0 = blockIdx.y * 128;
    const int n0 = blockIdx.x * 64;
    const int wm = (wid & 3) * 32;
    const int wn = (wid >> 2) * 32;

    int ar[4], ac[4], br[2], bc[2];
    #pragma unroll
    for (int i = 0; i < 4; i++) { int f = tid + i * 256; ar[i] = f >> 3; ac[i] = f & 7; }
    #pragma unroll
    for (int i = 0; i < 2; i++) { int f = tid + i * 256; br[i] = f >> 3; bc[i] = f & 7; }

    float acc[2][4][4] = {};

    // issue stage 0 (k0 = 0)
    #pragma unroll
    for (int i = 0; i < 4; i++)
        CP16(smb + (0 * QA_ST + ar[i] * 40 + ac[i] * 4) * 4,
             g_att + (size_t)(m0 + ar[i]) * CDIM + ac[i] * 4);
    #pragma unroll
    for (int i = 0; i < 2; i++)
        CP16(smb + (2 * QA_ST + 0 * QB_ST + br[i] * 40 + bc[i] * 4) * 4,
             g_wqr + (size_t)(n0 + br[i]) * CDIM + bc[i] * 4);
    CP_COMMIT();

    for (int it = 0; it < CDIM / 32; it++) {
        CP_WAIT0();
        __syncthreads();

        if (it + 1 < CDIM / 32) {
            int k0 = (it + 1) * 32;
            int ns = (it + 1) & 1;
            #pragma unroll
            for (int i = 0; i < 4; i++)
                CP16(smb + (ns * QA_ST + ar[i] * 40 + ac[i] * 4) * 4,
                     g_att + (size_t)(m0 + ar[i]) * CDIM + k0 + ac[i] * 4);
            #pragma unroll
            for (int i = 0; i < 2; i++)
                CP16(smb + (2 * QA_ST + ns * QB_ST + br[i] * 40 + bc[i] * 4) * 4,
                     g_wqr + (size_t)(n0 + br[i]) * CDIM + k0 + bc[i] * 4);
            CP_COMMIT();
        }

        const uint32_t* As = smq + (it & 1) * QA_ST;
        const uint32_t* Bs = smq + 2 * QA_ST + (it & 1) * QB_ST;

        #pragma unroll
        for (int kk = 0; kk < 32; kk += 8) {
            uint32_t a[2][4], b[4][2];
            #pragma unroll
            for (int mt = 0; mt < 2; mt++) {
                int r = wm + mt * 16;
                uint2 x0 = *(const uint2*)&As[(r + g    ) * 40 + kk + 2 * t];
                uint2 x1 = *(const uint2*)&As[(r + g + 8) * 40 + kk + 2 * t];
                a[mt][0] = x0.x; a[mt][1] = x1.x; a[mt][2] = x0.y; a[mt][3] = x1.y;
            }
            #pragma unroll
            for (int nt = 0; nt < 4; nt++) {
                uint2 y = *(const uint2*)&Bs[(wn + nt * 8 + g) * 40 + kk + 2 * t];
                b[nt][0] = y.x; b[nt][1] = y.y;
            }
            #pragma unroll
            for (int mt = 0; mt < 2; mt++)
                #pragma unroll
                for (int nt = 0; nt < 4; nt++)
                    mma8(acc[mt][nt], a[mt][0], a[mt][1], a[mt][2], a[mt][3],
                         b[nt][0], b[nt][1]);
        }
        __syncthreads();
    }

    const int which = n0 / CDIM;
    const int hh = (n0 % CDIM) / HDIM;
    if (which == 2) {
        // V: write transposed [B,H,D,N], tf32-rounded
        #pragma unroll
        for (int mt = 0; mt < 2; mt++) {
            #pragma unroll
            for (int e = 0; e < 2; e++) {
                int row = m0 + wm + mt * 16 + g + e * 8;
                int bb = row >> 11, nn = row & 2047;
                float* base = g_vt + (size_t)(bb * HEADS + hh) * HDIM * NSEQ + nn;
                #pragma unroll
                for (int nt = 0; nt < 4; nt++) {
                    int d = wn + nt * 8 + 2 * t;
                    base[(size_t)d * NSEQ]       = __uint_as_float(f2t(acc[mt][nt][e * 2]));
                    base[(size_t)(d + 1) * NSEQ] = __uint_as_float(f2t(acc[mt][nt][e * 2 + 1]));
                }
            }
        }
    } else {
        float* dst = (which == 0) ? g_q : g_k;
        const float mul = (which == 0) ? QSCALE : 1.0f;
        #pragma unroll
        for (int mt = 0; mt < 2; mt++) {
            #pragma unroll
            for (int e = 0; e < 2; e++) {
                int row = m0 + wm + mt * 16 + g + e * 8;
                int bb = row >> 11, nn = row & 2047;
                float* base = dst + ((size_t)(bb * HEADS + hh) * NSEQ + nn) * HDIM
                              + wn + 2 * t;
                #pragma unroll
                for (int nt = 0; nt < 4; nt++) {
                    float2 v;
                    v.x = __uint_as_float(f2t(acc[mt][nt][e * 2]     * mul));
                    v.y = __uint_as_float(f2t(acc[mt][nt][e * 2 + 1] * mul));
                    *(float2*)(base + nt * 8) = v;
                }
            }
        }
    }
}

// ---------------------------------------------------------------------------
// Kernel 2: flash attention. BM=128 q rows, key tile 64, 8 warps x 16 rows.
// Q fragments register-resident. K/V^T via cp.async double-buffer.
// P never touches smem: the S C-fragment is exactly the PV A-fragment under
// the shared k-reorder, so ex2 results feed the PV mma directly.
// ---------------------------------------------------------------------------
#define KVW  (64 * 72)            // words per K (or V) tile buffer

__global__ __launch_bounds__(256, 2) void flash_attn() {
    extern __shared__ float sm[];
    uint32_t smb;
    { uint64_t a = __cvta_generic_to_shared(sm); smb = (uint32_t)a; }

    const int tid = threadIdx.x;
    const int wid = tid >> 5, lane = tid & 31;
    const int g = lane >> 2, t = lane & 3;
    const int qn0 = blockIdx.x * 128;
    const int h = blockIdx.y, b = blockIdx.z;
    const size_t HO = (size_t)(b * HEADS + h) * NSEQ * HDIM;
    const float* Q  = g_q  + HO;
    const float* K  = g_k  + HO;
    const float* VT = g_vt + HO;
    const int qrow = wid * 16;

    int kr[4], kc[4];
    #pragma unroll
    for (int i = 0; i < 4; i++) { int f = tid + i * 256; kr[i] = f >> 4; kc[i] = f & 15; }

    // Q fragments -> registers (8 k-blocks of HDIM)
    uint32_t qa[8][4];
    {
        const float* q0 = Q + (size_t)(qn0 + qrow + g) * HDIM + 2 * t;
        const float* q1 = q0 + 8 * HDIM;
        #pragma unroll
        for (int kk8 = 0; kk8 < 8; kk8++) {
            float2 x0 = *(const float2*)(q0 + kk8 * 8);
            float2 x1 = *(const float2*)(q1 + kk8 * 8);
            qa[kk8][0] = fb(x0.x); qa[kk8][1] = fb(x1.x);
            qa[kk8][2] = fb(x0.y); qa[kk8][3] = fb(x1.y);
        }
    }

    // prologue: issue stage 0
    #pragma unroll
    for (int i = 0; i < 4; i++) {
        CP16(smb + (0 * 2 * KVW + kr[i] * 72 + kc[i] * 4) * 4,
             K + (size_t)kr[i] * HDIM + kc[i] * 4);
        CP16(smb + (0 * 2 * KVW + KVW + kr[i] * 72 + kc[i] * 4) * 4,
             VT + (size_t)kr[i] * NSEQ + kc[i] * 4);
    }
    CP_COMMIT();

    float li0 = 0.f, li1 = 0.f;
    float o[8][4] = {};
    int stage = 0;

    for (int kt = 0; kt < NSEQ; kt += 64) {
        CP_WAIT0();
        __syncthreads();

        if (kt + 64 < NSEQ) {
            int ns = stage ^ 1;
            #pragma unroll
            for (int i = 0; i < 4; i++) {
                CP16(smb + (ns * 2 * KVW + kr[i] * 72 + kc[i] * 4) * 4,
                     K + (size_t)(kt + 64 + kr[i]) * HDIM + kc[i] * 4);
                CP16(smb + (ns * 2 * KVW + KVW + kr[i] * 72 + kc[i] * 4) * 4,
                     VT + (size_t)kr[i] * NSEQ + kt + 64 + kc[i] * 4);
            }
            CP_COMMIT();
        }

        const float* Ks = sm + stage * 2 * KVW;
        const float* Vs = Ks + KVW;

        // S = Q @ K^T  (warp: 16 x 64), log2 domain
        float s[8][4] = {};
        #pragma unroll
        for (int kk8 = 0; kk8 < 8; kk8++) {
            #pragma unroll
            for (int nt = 0; nt < 8; nt++) {
                float2 kb = *(const float2*)&Ks[(nt * 8 + g) * 72 + kk8 * 8 + 2 * t];
                mma8(s[nt], qa[kk8][0], qa[kk8][1], qa[kk8][2], qa[kk8][3],
                     fb(kb.x), fb(kb.y));
            }
        }

        // P = 2^S in-register; pf[nt] holds the PV A-fragment for k-block nt:
        // a0=(g,2t)=p0, a1=(g+8,2t)=p2, a2=(g,2t+1)=p1, a3=(g+8,2t+1)=p3
        uint32_t pf[8][4];
        #pragma unroll
        for (int nt = 0; nt < 8; nt++) {
            float p0 = ex2(s[nt][0]), p1 = ex2(s[nt][1]);
            float p2 = ex2(s[nt][2]), p3 = ex2(s[nt][3]);
            li0 += p0 + p1;
            li1 += p2 + p3;
            pf[nt][0] = f2t(p0); pf[nt][1] = f2t(p2);
            pf[nt][2] = f2t(p1); pf[nt][3] = f2t(p3);
        }

        // O += P @ V  (warp: 16 x 64): A from registers, B from smem V^T
        #pragma unroll
        for (int kk8 = 0; kk8 < 8; kk8++) {
            #pragma unroll
            for (int nt = 0; nt < 8; nt++) {
                float2 vb = *(const float2*)&Vs[(nt * 8 + g) * 72 + kk8 * 8 + 2 * t];
                mma8(o[nt], pf[kk8][0], pf[kk8][1], pf[kk8][2], pf[kk8][3],
                     fb(vb.x), fb(vb.y));
            }
        }

        stage ^= 1;
    }

    li0 += __shfl_xor_sync(0xffffffffu, li0, 1);
    li0 += __shfl_xor_sync(0xffffffffu, li0, 2);
    li1 += __shfl_xor_sync(0xffffffffu, li1, 1);
    li1 += __shfl_xor_sync(0xffffffffu, li1, 2);

    // Epilogue: normalize, pre-round tf32, write [B,N,C]
    #pragma unroll
    for (int e = 0; e < 2; e++) {
        float inv = 1.f / (e == 0 ? li0 : li1);
        int row = qn0 + qrow + g + 8 * e;
        float* base = g_att + ((size_t)(b * NSEQ + row)) * CDIM + h * HDIM + 2 * t;
        #pragma unroll
        for (int nt = 0; nt < 8; nt++) {
            float2 v;
            v.x = __uint_as_float(f2t(o[nt][e*2+0] * inv));
            v.y = __uint_as_float(f2t(o[nt][e*2+1] * inv));
            *(float2*)(base + nt * 8) = v;
        }
    }
}

// ---------------------------------------------------------------------------
// Kernel 3: output projection on pre-rounded data (g_att from flash, g_wpr).
// cp.async double-buffered raw fills; LDS.64 fragments.
// ---------------------------------------------------------------------------
__global__ __launch_bounds__(256) void proj_gemm(const float* __restrict__ bias,
                                                 float* __restrict__ out) {
    extern __shared__ uint32_t smq[];   // As[2][128][40] | Bs[2][64][40]
    uint32_t smb;
    { uint64_t a = __cvta_generic_to_shared(smq); smb = (uint32_t)a; }

    const int tid = threadIdx.x;
    const int wid = tid >> 5, lane = tid & 31;
    const int g = lane >> 2, t = lane & 3;
    const int m0 = blockIdx.y * 128;
    const int n0 = blockIdx.x * 64;
    const int wm = (wid & 3) * 32;
    const int wn = (wid >> 2) * 32;

    int ar[4], ac[4], br[2], bc[2];
    #pragma unroll
    for (int i = 0; i < 4; i++) { int f = tid + i * 256; ar[i] = f >> 3; ac[i] = f & 7; }
    #pragma unroll
    for (int i = 0; i < 2; i++) { int f = tid + i * 256; br[i] = f >> 3; bc[i] = f & 7; }

    float acc[2][4][4] = {};

    #pragma unroll
    for (int i = 0; i < 4; i++)
        CP16(smb + (0 * QA_ST + ar[i] * 40 + ac[i] * 4) * 4,
             g_att + (size_t)(m0 + ar[i]) * CDIM + ac[i] * 4);
    #pragma unroll
    for (int i = 0; i < 2; i++)
        CP16(smb + (2 * QA_ST + 0 * QB_ST + br[i] * 40 + bc[i] * 4) * 4,
             g_wpr + (size_t)(n0 + br[i]) * CDIM + bc[i] * 4);
    CP_COMMIT();

    for (int it = 0; it < CDIM / 32; it++) {
        CP_WAIT0();
        __syncthreads();

        if (it + 1 < CDIM / 32) {
            int k0 = (it + 1) * 32;
            int ns = (it + 1) & 1;
            #pragma unroll
            for (int i = 0; i < 4; i++)
                CP16(smb + (ns * QA_ST + ar[i] * 40 + ac[i] * 4) * 4,
                     g_att + (size_t)(m0 + ar[i]) * CDIM + k0 + ac[i] * 4);
            #pragma unroll
            for (int i = 0; i < 2; i++)
                CP16(smb + (2 * QA_ST + ns * QB_ST + br[i] * 40 + bc[i] * 4) * 4,
                     g_wpr + (size_t)(n0 + br[i]) * CDIM + k0 + bc[i] * 4);
            CP_COMMIT();
        }

        const uint32_t* As = smq + (it & 1) * QA_ST;
        const uint32_t* Bs = smq + 2 * QA_ST + (it & 1) * QB_ST;

        #pragma unroll
        for (int kk = 0; kk < 32; kk += 8) {
            uint32_t a[2][4], b[4][2];
            #pragma unroll
            for (int mt = 0; mt < 2; mt++) {
                int r = wm + mt * 16;
                uint2 x0 = *(const uint2*)&As[(r + g    ) * 40 + kk + 2 * t];
                uint2 x1 = *(const uint2*)&As[(r + g + 8) * 40 + kk + 2 * t];
                a[mt][0] = x0.x; a[mt][1] = x1.x; a[mt][2] = x0.y; a[mt][3] = x1.y;
            }
            #pragma unroll
            for (int nt = 0; nt < 4; nt++) {
                uint2 y = *(const uint2*)&Bs[(wn + nt * 8 + g) * 40 + kk + 2 * t];
                b[nt][0] = y.x; b[nt][1] = y.y;
            }
            #pragma unroll
            for (int mt = 0; mt < 2; mt++)
                #pragma unroll
                for (int nt = 0; nt < 4; nt++)
                    mma8(acc[mt][nt], a[mt][0], a[mt][1], a[mt][2], a[mt][3],
                         b[nt][0], b[nt][1]);
        }
        __syncthreads();
    }

    #pragma unroll
    for (int mt = 0; mt < 2; mt++) {
        #pragma unroll
        for (int e = 0; e < 2; e++) {
            int row = m0 + wm + mt * 16 + g + e * 8;
            float* base = out + (size_t)row * CDIM + n0 + wn + 2 * t;
            const float* bb = bias + n0 + wn + 2 * t;
            #pragma unroll
            for (int nt = 0; nt < 4; nt++) {
                float2 v;
                v.x = acc[mt][nt][e * 2]     + bb[nt * 8];
                v.y = acc[mt][nt][e * 2 + 1] + bb[nt * 8 + 1];
                *(float2*)(base + nt * 8) = v;
            }
        }
    }
}

extern "C" void kernel_launch(void* const* d_in, const int* in_sizes, int n_in,
                              void* d_out, int out_size) {
    const float* x      = (const float*)d_in[0];  // [8,2048,320]
    const float* w_qkv  = (const float*)d_in[1];  // [960,320]
    const float* w_proj = (const float*)d_in[2];  // [320,320]
    const float* b_proj = (const float*)d_in[3];  // [320]
    float* out = (float*)d_out;

    const int gemm_smem  = (2 * QA_ST + 2 * QB_ST) * 4;   // 61440 B
    const int flash_smem = 4 * KVW * 4;                   // 73728 B
    cudaFuncSetAttribute(qkv_gemm,   cudaFuncAttributeMaxDynamicSharedMemorySize, gemm_smem);
    cudaFuncSetAttribute(flash_attn, cudaFuncAttributeMaxDynamicSharedMemorySize, flash_smem);
    cudaFuncSetAttribute(proj_gemm,  cudaFuncAttributeMaxDynamicSharedMemorySize, gemm_smem);

    pre_round<<<(PRE_TOTAL + 255) / 256, 256>>>(x, w_qkv, w_proj);

    dim3 g1(3 * CDIM / 64, MTOT / 128);   // (15, 128)
    qkv_gemm<<<g1, 256, gemm_smem>>>();

    dim3 g2(NSEQ / 128, HEADS, BATCH);    // (16, 5, 8)
    flash_attn<<<g2, 256, flash_smem>>>();

    dim3 g3(CDIM / 64, MTOT / 128);       // (5, 128)
    proj_gemm<<<g3, 256, gemm_smem>>>(b_proj, out);
}

// round 8
// speedup vs baseline: 1.5080x; 1.5080x over previous
#include <cuda_runtime.h>
#include <cuda_bf16.h>
#include <cstdint>

#define BATCH 8
#define NSEQ 2048
#define CDIM 320
#define HEADS 5
#define HDIM 64
#define MTOT (BATCH*NSEQ)      // 16384
#define QSCALE (0.125f * 1.4426950408889634f)   // scale * log2(e), folded into Q

// Scratch (static device globals; values pre-rounded to tf32 by producers)
__device__ float g_q [BATCH*HEADS*NSEQ*HDIM];   // [B,H,N,D]
__device__ float g_k [BATCH*HEADS*NSEQ*HDIM];   // [B,H,N,D]
__device__ float g_vt[BATCH*HEADS*HDIM*NSEQ];   // [B,H,D,N]  (V transposed)
__device__ float g_att[MTOT*CDIM];

__device__ __forceinline__ uint32_t f2t(float x) {
    uint32_t u;
    asm("cvt.rna.tf32.f32 %0, %1;" : "=r"(u) : "f"(x));
    return u;
}
__device__ __forceinline__ float ex2(float x) {
    float y;
    asm("ex2.approx.f32 %0, %1;" : "=f"(y) : "f"(x));
    return y;
}
__device__ __forceinline__ uint32_t fb(float x) { return __float_as_uint(x); }

// D = A(16x8,row) * B(8x8,col) + D, tf32 in, fp32 accum
__device__ __forceinline__ void mma8(float* c,
                                     uint32_t a0, uint32_t a1, uint32_t a2, uint32_t a3,
                                     uint32_t b0, uint32_t b1) {
    asm volatile(
        "mma.sync.aligned.m16n8k8.row.col.f32.tf32.tf32.f32 "
        "{%0,%1,%2,%3}, {%4,%5,%6,%7}, {%8,%9}, {%0,%1,%2,%3};"
        : "+f"(c[0]), "+f"(c[1]), "+f"(c[2]), "+f"(c[3])
        : "r"(a0), "r"(a1), "r"(a2), "r"(a3), "r"(b0), "r"(b1));
}

#define CP16(dst_u32, src) \
    asm volatile("cp.async.cg.shared.global [%0], [%1], 16;" :: "r"(dst_u32), "l"(src))
#define CP_COMMIT() asm volatile("cp.async.commit_group;")
#define CP_WAIT0()  asm volatile("cp.async.wait_group 0;")

// ---------------------------------------------------------------------------
// Kernel 1: QKV GEMM. BM=128, BN=64, BK=32, 8 warps, warp tile 32x32.
// Fragment loads are LDS.64 of adjacent k-positions (k-reorder trick: A and B
// use the same in-block k order, so the mma pairing stays consistent).
// Epilogue pre-rounds to tf32; Q pre-scaled by scale*log2e; V transposed.
// ---------------------------------------------------------------------------
__global__ __launch_bounds__(256) void qkv_gemm(const float* __restrict__ X,
                                                const float* __restrict__ W) {
    __shared__ uint32_t As[128][40];
    __shared__ uint32_t Bs[64][40];
    const int tid = threadIdx.x;
    const int wid = tid >> 5, lane = tid & 31;
    const int g = lane >> 2, t = lane & 3;
    const int m0 = blockIdx.y * 128;
    const int n0 = blockIdx.x * 64;
    const int wm = (wid & 3) * 32;
    const int wn = (wid >> 2) * 32;

    int ar[4], ac[4], br[2], bc[2];
    #pragma unroll
    for (int i = 0; i < 4; i++) { int f = tid + i * 256; ar[i] = f >> 3; ac[i] = f & 7; }
    #pragma unroll
    for (int i = 0; i < 2; i++) { int f = tid + i * 256; br[i] = f >> 3; bc[i] = f & 7; }

    float acc[2][4][4] = {};
    float4 pa[4], pb[2];

    #pragma unroll
    for (int i = 0; i < 4; i++)
        pa[i] = *(const float4*)(X + (size_t)(m0 + ar[i]) * CDIM + ac[i] * 4);
    #pragma unroll
    for (int i = 0; i < 2; i++)
        pb[i] = *(const float4*)(W + (size_t)(n0 + br[i]) * CDIM + bc[i] * 4);

    for (int it = 0; it < CDIM / 32; it++) {
        __syncthreads();
        #pragma unroll
        for (int i = 0; i < 4; i++) {
            float4 v = pa[i];
            uint32_t tmp[4] = {f2t(v.x), f2t(v.y), f2t(v.z), f2t(v.w)};
            *(float4*)&As[ar[i]][ac[i] * 4] = *(float4*)tmp;
        }
        #pragma unroll
        for (int i = 0; i < 2; i++) {
            float4 v = pb[i];
            uint32_t tmp[4] = {f2t(v.x), f2t(v.y), f2t(v.z), f2t(v.w)};
            *(float4*)&Bs[br[i]][bc[i] * 4] = *(float4*)tmp;
        }
        __syncthreads();

        if (it + 1 < CDIM / 32) {
            int k0 = (it + 1) * 32;
            #pragma unroll
            for (int i = 0; i < 4; i++)
                pa[i] = *(const float4*)(X + (size_t)(m0 + ar[i]) * CDIM + k0 + ac[i] * 4);
            #pragma unroll
            for (int i = 0; i < 2; i++)
                pb[i] = *(const float4*)(W + (size_t)(n0 + br[i]) * CDIM + k0 + bc[i] * 4);
        }

        #pragma unroll
        for (int kk = 0; kk < 32; kk += 8) {
            uint32_t a[2][4], b[4][2];
            #pragma unroll
            for (int mt = 0; mt < 2; mt++) {
                int r = wm + mt * 16;
                uint2 x0 = *(uint2*)&As[r + g    ][kk + 2 * t];
                uint2 x1 = *(uint2*)&As[r + g + 8][kk + 2 * t];
                a[mt][0] = x0.x; a[mt][1] = x1.x; a[mt][2] = x0.y; a[mt][3] = x1.y;
            }
            #pragma unroll
            for (int nt = 0; nt < 4; nt++) {
                uint2 y = *(uint2*)&Bs[wn + nt * 8 + g][kk + 2 * t];
                b[nt][0] = y.x; b[nt][1] = y.y;
            }
            #pragma unroll
            for (int mt = 0; mt < 2; mt++)
                #pragma unroll
                for (int nt = 0; nt < 4; nt++)
                    mma8(acc[mt][nt], a[mt][0], a[mt][1], a[mt][2], a[mt][3],
                         b[nt][0], b[nt][1]);
        }
        __syncthreads();
    }

    const int which = n0 / CDIM;
    const int hh = (n0 % CDIM) / HDIM;
    if (which == 2) {
        // V: write transposed [B,H,D,N], tf32-rounded
        #pragma unroll
        for (int mt = 0; mt < 2; mt++) {
            #pragma unroll
            for (int e = 0; e < 2; e++) {
                int row = m0 + wm + mt * 16 + g + e * 8;
                int bb = row >> 11, nn = row & 2047;
                float* base = g_vt + (size_t)(bb * HEADS + hh) * HDIM * NSEQ + nn;
                #pragma unroll
                for (int nt = 0; nt < 4; nt++) {
                    int d = wn + nt * 8 + 2 * t;
                    base[(size_t)d * NSEQ]       = __uint_as_float(f2t(acc[mt][nt][e * 2]));
                    base[(size_t)(d + 1) * NSEQ] = __uint_as_float(f2t(acc[mt][nt][e * 2 + 1]));
                }
            }
        }
    } else {
        float* dst = (which == 0) ? g_q : g_k;
        const float mul = (which == 0) ? QSCALE : 1.0f;
        #pragma unroll
        for (int mt = 0; mt < 2; mt++) {
            #pragma unroll
            for (int e = 0; e < 2; e++) {
                int row = m0 + wm + mt * 16 + g + e * 8;
                int bb = row >> 11, nn = row & 2047;
                float* base = dst + ((size_t)(bb * HEADS + hh) * NSEQ + nn) * HDIM
                              + wn + 2 * t;
                #pragma unroll
                for (int nt = 0; nt < 4; nt++) {
                    float2 v;
                    v.x = __uint_as_float(f2t(acc[mt][nt][e * 2]     * mul));
                    v.y = __uint_as_float(f2t(acc[mt][nt][e * 2 + 1] * mul));
                    *(float2*)(base + nt * 8) = v;
                }
            }
        }
    }
}

// ---------------------------------------------------------------------------
// Kernel 2: flash attention. BM=128 q rows, key tile 64, 8 warps x 16 rows.
// Q fragments register-resident; K/V^T via cp.async double-buffer.
// P stays in registers: the QK^T C-fragment is converted IN PLACE (same array)
// into the PV A-fragment under the shared k-reorder — no extra pf array, so
// peak live regs ~ qa(32)+s(32)+o(32) and no spill under the 128 cap.
// ---------------------------------------------------------------------------
#define KVW  (64 * 72)            // words per K (or V) tile buffer

__global__ __launch_bounds__(256, 2) void flash_attn() {
    extern __shared__ float sm[];
    uint32_t smb;
    { uint64_t a = __cvta_generic_to_shared(sm); smb = (uint32_t)a; }

    const int tid = threadIdx.x;
    const int wid = tid >> 5, lane = tid & 31;
    const int g = lane >> 2, t = lane & 3;
    const int qn0 = blockIdx.x * 128;
    const int h = blockIdx.y, b = blockIdx.z;
    const size_t HO = (size_t)(b * HEADS + h) * NSEQ * HDIM;
    const float* Q  = g_q  + HO;
    const float* K  = g_k  + HO;
    const float* VT = g_vt + HO;
    const int qrow = wid * 16;

    int kr[4], kc[4];
    #pragma unroll
    for (int i = 0; i < 4; i++) { int f = tid + i * 256; kr[i] = f >> 4; kc[i] = f & 15; }

    // Q fragments -> registers (8 k-blocks of HDIM)
    uint32_t qa[8][4];
    {
        const float* q0 = Q + (size_t)(qn0 + qrow + g) * HDIM + 2 * t;
        const float* q1 = q0 + 8 * HDIM;
        #pragma unroll
        for (int kk8 = 0; kk8 < 8; kk8++) {
            float2 x0 = *(const float2*)(q0 + kk8 * 8);
            float2 x1 = *(const float2*)(q1 + kk8 * 8);
            qa[kk8][0] = fb(x0.x); qa[kk8][1] = fb(x1.x);
            qa[kk8][2] = fb(x0.y); qa[kk8][3] = fb(x1.y);
        }
    }

    // prologue: issue stage 0
    #pragma unroll
    for (int i = 0; i < 4; i++) {
        CP16(smb + (0 * 2 * KVW + kr[i] * 72 + kc[i] * 4) * 4,
             K + (size_t)kr[i] * HDIM + kc[i] * 4);
        CP16(smb + (0 * 2 * KVW + KVW + kr[i] * 72 + kc[i] * 4) * 4,
             VT + (size_t)kr[i] * NSEQ + kc[i] * 4);
    }
    CP_COMMIT();

    float li0 = 0.f, li1 = 0.f;
    float o[8][4] = {};
    int stage = 0;

    for (int kt = 0; kt < NSEQ; kt += 64) {
        CP_WAIT0();
        __syncthreads();

        if (kt + 64 < NSEQ) {
            int ns = stage ^ 1;
            #pragma unroll
            for (int i = 0; i < 4; i++) {
                CP16(smb + (ns * 2 * KVW + kr[i] * 72 + kc[i] * 4) * 4,
                     K + (size_t)(kt + 64 + kr[i]) * HDIM + kc[i] * 4);
                CP16(smb + (ns * 2 * KVW + KVW + kr[i] * 72 + kc[i] * 4) * 4,
                     VT + (size_t)kr[i] * NSEQ + kt + 64 + kc[i] * 4);
            }
            CP_COMMIT();
        }

        const float* Ks = sm + stage * 2 * KVW;
        const float* Vs = Ks + KVW;

        // S = Q @ K^T  (warp: 16 x 64), log2 domain
        float s[8][4] = {};
        #pragma unroll
        for (int kk8 = 0; kk8 < 8; kk8++) {
            #pragma unroll
            for (int nt = 0; nt < 8; nt++) {
                float2 kb = *(const float2*)&Ks[(nt * 8 + g) * 72 + kk8 * 8 + 2 * t];
                mma8(s[nt], qa[kk8][0], qa[kk8][1], qa[kk8][2], qa[kk8][3],
                     fb(kb.x), fb(kb.y));
            }
        }

        // P = 2^S, converted IN PLACE into PV A-fragment order:
        // C frag: c0=(g,2t) c1=(g,2t+1) c2=(g+8,2t) c3=(g+8,2t+1)
        // A frag (k-reordered): a0=(g,2t) a1=(g+8,2t) a2=(g,2t+1) a3=(g+8,2t+1)
        #pragma unroll
        for (int nt = 0; nt < 8; nt++) {
            float p0 = ex2(s[nt][0]), p1 = ex2(s[nt][1]);
            float p2 = ex2(s[nt][2]), p3 = ex2(s[nt][3]);
            li0 += p0 + p1;
            li1 += p2 + p3;
            s[nt][0] = __uint_as_float(f2t(p0));
            s[nt][1] = __uint_as_float(f2t(p2));
            s[nt][2] = __uint_as_float(f2t(p1));
            s[nt][3] = __uint_as_float(f2t(p3));
        }

        // O += P @ V  (warp: 16 x 64): A from registers (s), B from smem V^T
        #pragma unroll
        for (int kk8 = 0; kk8 < 8; kk8++) {
            #pragma unroll
            for (int nt = 0; nt < 8; nt++) {
                float2 vb = *(const float2*)&Vs[(nt * 8 + g) * 72 + kk8 * 8 + 2 * t];
                mma8(o[nt], fb(s[kk8][0]), fb(s[kk8][1]), fb(s[kk8][2]), fb(s[kk8][3]),
                     fb(vb.x), fb(vb.y));
            }
        }

        stage ^= 1;
    }

    li0 += __shfl_xor_sync(0xffffffffu, li0, 1);
    li0 += __shfl_xor_sync(0xffffffffu, li0, 2);
    li1 += __shfl_xor_sync(0xffffffffu, li1, 1);
    li1 += __shfl_xor_sync(0xffffffffu, li1, 2);

    // Epilogue: normalize, pre-round tf32, write [B,N,C]
    #pragma unroll
    for (int e = 0; e < 2; e++) {
        float inv = 1.f / (e == 0 ? li0 : li1);
        int row = qn0 + qrow + g + 8 * e;
        float* base = g_att + ((size_t)(b * NSEQ + row)) * CDIM + h * HDIM + 2 * t;
        #pragma unroll
        for (int nt = 0; nt < 8; nt++) {
            float2 v;
            v.x = __uint_as_float(f2t(o[nt][e*2+0] * inv));
            v.y = __uint_as_float(f2t(o[nt][e*2+1] * inv));
            *(float2*)(base + nt * 8) = v;
        }
    }
}

// ---------------------------------------------------------------------------
// Kernel 3: output projection. A (g_att) pre-rounded tf32 -> raw fills;
// LDS.64 fragment loads via the same k-reorder trick.
// ---------------------------------------------------------------------------
__global__ __launch_bounds__(256) void proj_gemm(const float* __restrict__ W,
                                                 const float* __restrict__ bias,
                                                 float* __restrict__ out) {
    __shared__ uint32_t As[128][40];
    __shared__ uint32_t Bs[64][40];
    const int tid = threadIdx.x;
    const int wid = tid >> 5, lane = tid & 31;
    const int g = lane >> 2, t = lane & 3;
    const int m0 = blockIdx.y * 128;
    const int n0 = blockIdx.x * 64;
    const int wm = (wid & 3) * 32;
    const int wn = (wid >> 2) * 32;

    int ar[4], ac[4], br[2], bc[2];
    #pragma unroll
    for (int i = 0; i < 4; i++) { int f = tid + i * 256; ar[i] = f >> 3; ac[i] = f & 7; }
    #pragma unroll
    for (int i = 0; i < 2; i++) { int f = tid + i * 256; br[i] = f >> 3; bc[i] = f & 7; }

    float acc[2][4][4] = {};
    float4 pa[4], pb[2];

    #pragma unroll
    for (int i = 0; i < 4; i++)
        pa[i] = *(const float4*)(g_att + (size_t)(m0 + ar[i]) * CDIM + ac[i] * 4);
    #pragma unroll
    for (int i = 0; i < 2; i++)
        pb[i] = *(const float4*)(W + (size_t)(n0 + br[i]) * CDIM + bc[i] * 4);

    for (int it = 0; it < CDIM / 32; it++) {
        __syncthreads();
        #pragma unroll
        for (int i = 0; i < 4; i++)
            *(float4*)&As[ar[i]][ac[i] * 4] = pa[i];
        #pragma unroll
        for (int i = 0; i < 2; i++) {
            float4 v = pb[i];
            uint32_t tmp[4] = {f2t(v.x), f2t(v.y), f2t(v.z), f2t(v.w)};
            *(float4*)&Bs[br[i]][bc[i] * 4] = *(float4*)tmp;
        }
        __syncthreads();

        if (it + 1 < CDIM / 32) {
            int k0 = (it + 1) * 32;
            #pragma unroll
            for (int i = 0; i < 4; i++)
                pa[i] = *(const float4*)(g_att + (size_t)(m0 + ar[i]) * CDIM + k0 + ac[i] * 4);
            #pragma unroll
            for (int i = 0; i < 2; i++)
                pb[i] = *(const float4*)(W + (size_t)(n0 + br[i]) * CDIM + k0 + bc[i] * 4);
        }

        #pragma unroll
        for (int kk = 0; kk < 32; kk += 8) {
            uint32_t a[2][4], b[4][2];
            #pragma unroll
            for (int mt = 0; mt < 2; mt++) {
                int r = wm + mt * 16;
                uint2 x0 = *(uint2*)&As[r + g    ][kk + 2 * t];
                uint2 x1 = *(uint2*)&As[r + g + 8][kk + 2 * t];
                a[mt][0] = x0.x; a[mt][1] = x1.x; a[mt][2] = x0.y; a[mt][3] = x1.y;
            }
            #pragma unroll
            for (int nt = 0; nt < 4; nt++) {
                uint2 y = *(uint2*)&Bs[wn + nt * 8 + g][kk + 2 * t];
                b[nt][0] = y.x; b[nt][1] = y.y;
            }
            #pragma unroll
            for (int mt = 0; mt < 2; mt++)
                #pragma unroll
                for (int nt = 0; nt < 4; nt++)
                    mma8(acc[mt][nt], a[mt][0], a[mt][1], a[mt][2], a[mt][3],
                         b[nt][0], b[nt][1]);
        }
        __syncthreads();
    }

    #pragma unroll
    for (int mt = 0; mt < 2; mt++) {
        #pragma unroll
        for (int e = 0; e < 2; e++) {
            int row = m0 + wm + mt * 16 + g + e * 8;
            float* base = out + (size_t)row * CDIM + n0 + wn + 2 * t;
            const float* bb = bias + n0 + wn + 2 * t;
            #pragma unroll
            for (int nt = 0; nt < 4; nt++) {
                float2 v;
                v.x = acc[mt][nt][e * 2]     + bb[nt * 8];
                v.y = acc[mt][nt][e * 2 + 1] + bb[nt * 8 + 1];
                *(float2*)(base + nt * 8) = v;
            }
        }
    }
}

extern "C" void kernel_launch(void* const* d_in, const int* in_sizes, int n_in,
                              void* d_out, int out_size) {
    const float* x      = (const float*)d_in[0];  // [8,2048,320]
    const float* w_qkv  = (const float*)d_in[1];  // [960,320]
    const float* w_proj = (const float*)d_in[2];  // [320,320]
    const float* b_proj = (const float*)d_in[3];  // [320]
    float* out = (float*)d_out;

    const int flash_smem = 4 * KVW * 4;   // 73728 B
    cudaFuncSetAttribute(flash_attn, cudaFuncAttributeMaxDynamicSharedMemorySize,
                         flash_smem);

    dim3 g1(3 * CDIM / 64, MTOT / 128);   // (15, 128)
    qkv_gemm<<<g1, 256>>>(x, w_qkv);

    dim3 g2(NSEQ / 128, HEADS, BATCH);    // (16, 5, 8)
    flash_attn<<<g2, 256, flash_smem>>>();

    dim3 g3(CDIM / 64, MTOT / 128);       // (5, 128)
    proj_gemm<<<g3, 256>>>(w_proj, b_proj, out);
}